// round 5
// baseline (speedup 1.0000x reference)
#include <cuda_runtime.h>

#define BB 16
#define LL 2048
#define HH 1024
#define ZZ 512

// Scratch (device globals; no allocation allowed)
__device__ float g_k[BB * HH];         // final @ Wk
__device__ float g_kq[BB * HH];        // Wq @ k
__device__ float g_w[BB * LL];         // logits, then NORMALIZED softmax weights
__device__ float g_part[32 * BB * ZZ]; // partial column sums of latent z
__device__ float g_S[BB * ZZ];         // (sum_i z[b,i]) @ Wv

// ---------------------------------------------------------------------------
// kA: k[b,h] = fin[b,:] . Wk[:,h].  128 blocks x 512 threads.
// ---------------------------------------------------------------------------
__global__ void __launch_bounds__(512) kA_kproj(
    const float* __restrict__ fin, const float* __restrict__ Wk)
{
    __shared__ float sh[HH];
    __shared__ float red[512];
    const int blk = blockIdx.x;
    const int t = threadIdx.x;
    const int b = blk >> 3;
    const int hof = t & 127;
    const int h = ((blk & 7) << 7) + hof;
    const int cs = t >> 7;
    for (int j = t; j < HH; j += 512) sh[j] = fin[b * HH + j];
    __syncthreads();
    float acc = 0.f;
    const float* wcol = Wk + h;
#pragma unroll 8
    for (int c = cs * 256; c < (cs + 1) * 256; ++c)
        acc += sh[c] * wcol[(size_t)c * HH];
    red[t] = acc;
    __syncthreads();
    if (cs == 0)
        g_k[b * HH + h] = red[hof] + red[128 + hof] + red[256 + hof] + red[384 + hof];
}

// ---------------------------------------------------------------------------
// kE: partial column sums of z. 512 blocks x 512 threads (side stream).
// ---------------------------------------------------------------------------
__global__ void __launch_bounds__(512) kE_zsum(const float* __restrict__ zin)
{
    const int e = blockIdx.x;
    const int t = threadIdx.x;
    const int b = e >> 5;
    const int chunk = e & 31;
    const float* base = zin + ((size_t)b * LL + (size_t)chunk * 64) * ZZ + t;
    float acc = 0.f;
#pragma unroll 16
    for (int i = 0; i < 64; ++i) acc += __ldcs(base + (size_t)i * ZZ);
    g_part[(chunk * BB + b) * ZZ + t] = acc;
}

// ---------------------------------------------------------------------------
// kF: S[b,:] = (sum of 32 partials) @ Wv. 16 blocks x 512 threads (side stream).
// ---------------------------------------------------------------------------
__global__ void __launch_bounds__(512) kF_sproj(const float* __restrict__ Wv)
{
    __shared__ float sh[ZZ];
    const int b = blockIdx.x;
    const int t = threadIdx.x;
    float acc = 0.f;
#pragma unroll
    for (int c = 0; c < 32; ++c) acc += g_part[(c * BB + b) * ZZ + t];
    sh[t] = acc;
    __syncthreads();
    float s = 0.f;
#pragma unroll 8
    for (int c = 0; c < ZZ; ++c) s += sh[c] * Wv[(size_t)c * ZZ + t];
    g_S[b * ZZ + t] = s;
}

// ---------------------------------------------------------------------------
// kB: kq[b,r] = Wq[r,:] . k[b,:].  1024 blocks x 512 threads, warp per row.
// ---------------------------------------------------------------------------
__global__ void __launch_bounds__(512) kB_kqproj(const float* __restrict__ Wq)
{
    __shared__ __align__(16) float sh[HH];
    const int blk = blockIdx.x;
    const int t = threadIdx.x;
    const int b = blk >> 6;
    for (int j = t; j < HH; j += 512) sh[j] = g_k[b * HH + j];
    __syncthreads();
    const int warp = t >> 5, lane = t & 31;
    const int r = (blk & 63) * 16 + warp;
    const float4* wrow = (const float4*)(Wq + (size_t)r * HH);
    const float4* sk4 = (const float4*)sh;
    float acc = 0.f;
#pragma unroll
    for (int c = lane; c < HH / 4; c += 32) {
        float4 wv = wrow[c];
        float4 kv = sk4[c];
        acc += wv.x * kv.x + wv.y * kv.y + wv.z * kv.z + wv.w * kv.w;
    }
#pragma unroll
    for (int o = 16; o; o >>= 1) acc += __shfl_xor_sync(0xffffffffu, acc, o);
    if (lane == 0) g_kq[b * HH + r] = acc;
}

// ---------------------------------------------------------------------------
// k3: raw masked logit. 2048 blocks x 512 threads, warp per row.
// ---------------------------------------------------------------------------
__global__ void __launch_bounds__(512) k3_logits(
    const float* __restrict__ enc, const int* __restrict__ mask)
{
    const int warp = threadIdx.x >> 5, lane = threadIdx.x & 31;
    const int row = blockIdx.x * 16 + warp;
    const int b = row >> 11;
    const float4* e4 = (const float4*)(enc + (size_t)row * HH);
    const float4* kq4 = (const float4*)(g_kq + b * HH);
    float acc = 0.f;
#pragma unroll
    for (int c = lane; c < HH / 4; c += 32) {
        float4 ev = __ldcs(&e4[c]);
        float4 kv = __ldg(&kq4[c]);
        acc += ev.x * kv.x + ev.y * kv.y + ev.z * kv.z + ev.w * kv.w;
    }
#pragma unroll
    for (int o = 16; o; o >>= 1) acc += __shfl_xor_sync(0xffffffffu, acc, o);
    if (lane == 0) {
        float val = acc * 0.03125f;
        if (mask[row] == 0) val = -1e9f;
        g_w[row] = val;
    }
}

// ---------------------------------------------------------------------------
// k4: normalize g_w in place to final softmax weights. 16 blocks x 256 threads.
// ---------------------------------------------------------------------------
__global__ void __launch_bounds__(256) k4_norm()
{
    __shared__ float red[8];
    __shared__ float s_max, s_inv;
    const int b = blockIdx.x, t = threadIdx.x;
    const int warp = t >> 5, lane = t & 31;

    float lg[8];
#pragma unroll
    for (int k = 0; k < 8; ++k) lg[k] = g_w[b * LL + k * 256 + t];

    float m = lg[0];
#pragma unroll
    for (int k = 1; k < 8; ++k) m = fmaxf(m, lg[k]);
#pragma unroll
    for (int o = 16; o; o >>= 1) m = fmaxf(m, __shfl_xor_sync(0xffffffffu, m, o));
    if (lane == 0) red[warp] = m;
    __syncthreads();
    if (warp == 0 && lane < 8) {
        float v = red[lane];
#pragma unroll
        for (int o = 4; o; o >>= 1) v = fmaxf(v, __shfl_xor_sync(0xffu, v, o));
        if (lane == 0) s_max = v;
    }
    __syncthreads();
    const float M = s_max;

    float e[8];
    float s = 0.f;
#pragma unroll
    for (int k = 0; k < 8; ++k) { e[k] = __expf(lg[k] - M); s += e[k]; }
#pragma unroll
    for (int o = 16; o; o >>= 1) s += __shfl_xor_sync(0xffffffffu, s, o);
    __syncthreads();
    if (lane == 0) red[warp] = s;
    __syncthreads();
    if (warp == 0 && lane < 8) {
        float v = red[lane];
#pragma unroll
        for (int o = 4; o; o >>= 1) v += __shfl_xor_sync(0xffu, v, o);
        if (lane == 0) s_inv = 1.f / v;
    }
    __syncthreads();
    const float inv = s_inv;

#pragma unroll
    for (int k = 0; k < 8; ++k) g_w[b * LL + k * 256 + t] = e[k] * inv;
}

// ---------------------------------------------------------------------------
// k5: pure streaming writer (no preamble). 5120 blocks x 256 threads,
// 16 float4 stores per thread.
//   blocks [0,4096)    : attn (8 rows/block, weights hoisted)
//   blocks [4096,5120) : out (32 rows/block, S-float4 hoisted)
// ---------------------------------------------------------------------------
__global__ void __launch_bounds__(256) k5_write(float* __restrict__ out)
{
    const int blk = blockIdx.x;
    const int t = threadIdx.x;

    if (blk < 4096) {
        const int b = blk >> 8;
        const long long base = (long long)b * (LL * LL / 4)
                             + (long long)(blk & 255) * 4096;
        const int rowbase = (int)(base >> 9);
        float4* attn4 = (float4*)(out + (size_t)BB * LL * ZZ);
        float w8[8];
#pragma unroll
        for (int j = 0; j < 8; ++j) w8[j] = __ldg(&g_w[rowbase + j]);
#pragma unroll
        for (int k = 0; k < 16; ++k) {
            const float wv = w8[k >> 1];
            __stcs(attn4 + base + k * 256 + t, make_float4(wv, wv, wv, wv));
        }
    } else {
        const int e = blk - 4096;
        const int b = e >> 6;
        const long long base = (long long)b * (LL * ZZ / 4)
                             + (long long)(e & 63) * 4096;
        const int rowbase = (int)(base >> 7);
        const int rsub = t >> 7;              // 0 or 1
        const float4 sv = __ldg((const float4*)g_S + b * (ZZ / 4) + (t & 127));
#pragma unroll
        for (int k = 0; k < 16; ++k) {
            const float wv = __ldg(&g_w[rowbase + 2 * k + rsub]);
            __stcs((float4*)out + base + k * 256 + t,
                   make_float4(wv * sv.x, wv * sv.y, wv * sv.z, wv * sv.w));
        }
    }
}

// ---------------------------------------------------------------------------
extern "C" void kernel_launch(void* const* d_in, const int* in_sizes, int n_in,
                              void* d_out, int out_size)
{
    const float* enc  = (const float*)d_in[0];
    const float* fin  = (const float*)d_in[1];
    const float* zseq = (const float*)d_in[2];
    const int*   mask = (const int*)  d_in[3];
    const float* Wq   = (const float*)d_in[4];
    const float* Wk   = (const float*)d_in[5];
    const float* Wv   = (const float*)d_in[6];
    float* out = (float*)d_out;

    // Fork a side stream for the independent z-sum branch (E -> F).
    cudaStream_t s1;
    cudaStreamCreateWithFlags(&s1, cudaStreamNonBlocking);
    cudaEvent_t e_fork, e_join;
    cudaEventCreateWithFlags(&e_fork, cudaEventDisableTiming);
    cudaEventCreateWithFlags(&e_join, cudaEventDisableTiming);

    cudaEventRecord(e_fork, 0);
    cudaStreamWaitEvent(s1, e_fork, 0);
    kE_zsum<<<512, 512, 0, s1>>>(zseq);
    kF_sproj<<<16, 512, 0, s1>>>(Wv);
    cudaEventRecord(e_join, s1);

    // Main chain: A -> B -> logits -> normalize
    kA_kproj<<<128, 512>>>(fin, Wk);
    kB_kqproj<<<1024, 512>>>(Wq);
    k3_logits<<<2048, 512>>>(enc, mask);
    k4_norm<<<16, 256>>>();

    // Join and write
    cudaStreamWaitEvent(0, e_join, 0);
    k5_write<<<5120, 256>>>(out);

    cudaEventDestroy(e_fork);
    cudaEventDestroy(e_join);
    cudaStreamDestroy(s1);
}

// round 6
// speedup vs baseline: 1.0099x; 1.0099x over previous
#include <cuda_runtime.h>

#define BB 16
#define LL 2048
#define HH 1024
#define ZZ 512

// Scratch (device globals; no allocation allowed)
__device__ float g_k[BB * HH];         // final @ Wk
__device__ float g_kq[BB * HH];        // Wq @ k
__device__ float g_w[BB * LL];         // logits, then NORMALIZED softmax weights
__device__ float g_part[32 * BB * ZZ]; // partial column sums of latent z
__device__ float g_S[BB * ZZ];         // (sum_i z[b,i]) @ Wv

// ---------------------------------------------------------------------------
// kE helper: one block = one (batch, 64-row chunk) partial column sum of z.
// ---------------------------------------------------------------------------
__device__ __forceinline__ void zsum_block(const float* __restrict__ zin, int e, int t)
{
    const int b = e >> 5;
    const int chunk = e & 31;
    const float* base = zin + ((size_t)b * LL + (size_t)chunk * 64) * ZZ + t;
    float acc = 0.f;
#pragma unroll 16
    for (int i = 0; i < 64; ++i) acc += __ldcs(base + (size_t)i * ZZ);
    g_part[(chunk * BB + b) * ZZ + t] = acc;
}

// ---------------------------------------------------------------------------
// L1: blocks [0,128)   -> kA: k[b,h] = fin[b,:] . Wk[:,h]
//     blocks [128,384) -> kE chunks [0,256)
// ---------------------------------------------------------------------------
__global__ void __launch_bounds__(512) k1_a_e(
    const float* __restrict__ fin, const float* __restrict__ Wk,
    const float* __restrict__ zin)
{
    __shared__ float sh[HH];
    __shared__ float red[512];
    const int blk = blockIdx.x;
    const int t = threadIdx.x;

    if (blk < 128) {
        const int b = blk >> 3;
        const int hof = t & 127;
        const int h = ((blk & 7) << 7) + hof;
        const int cs = t >> 7;
        for (int j = t; j < HH; j += 512) sh[j] = fin[b * HH + j];
        __syncthreads();
        float acc = 0.f;
        const float* wcol = Wk + h;
#pragma unroll 8
        for (int c = cs * 256; c < (cs + 1) * 256; ++c)
            acc += sh[c] * wcol[(size_t)c * HH];
        red[t] = acc;
        __syncthreads();
        if (cs == 0)
            g_k[b * HH + h] = red[hof] + red[128 + hof] + red[256 + hof] + red[384 + hof];
    } else {
        zsum_block(zin, blk - 128, t);
    }
}

// ---------------------------------------------------------------------------
// L2: blocks [0,128)   -> kB batch-shared: 64 row-blocks x 2 batch-groups.
//       Block (rb, bg): smem holds 8 k-vectors (batches 8bg..8bg+7, 32 KB);
//       warp w handles Wq row r = rb*16+w, dotted against all 8 at once.
//     blocks [128,384) -> kE chunks [256,512)
// ---------------------------------------------------------------------------
__global__ void __launch_bounds__(512) k2_b_e(
    const float* __restrict__ Wq, const float* __restrict__ zin)
{
    __shared__ __align__(16) float sk[8 * HH];      // 32 KB
    const int blk = blockIdx.x;
    const int t = threadIdx.x;

    if (blk < 128) {
        const int rb = blk >> 1;            // 0..63
        const int bg = blk & 1;             // batches 8bg..8bg+7
        // load 8 k-vectors
        for (int j = t; j < 8 * HH; j += 512)
            sk[j] = g_k[(8 * bg + (j >> 10)) * HH + (j & 1023)];
        __syncthreads();

        const int warp = t >> 5, lane = t & 31;
        const int r = rb * 16 + warp;
        const float4* wrow = (const float4*)(Wq + (size_t)r * HH);
        float acc[8] = {0.f, 0.f, 0.f, 0.f, 0.f, 0.f, 0.f, 0.f};
#pragma unroll 2
        for (int c = lane; c < HH / 4; c += 32) {
            const float4 wv = wrow[c];
#pragma unroll
            for (int j = 0; j < 8; ++j) {
                const float4 kv = ((const float4*)(sk + j * HH))[c];
                acc[j] += wv.x * kv.x + wv.y * kv.y + wv.z * kv.z + wv.w * kv.w;
            }
        }
#pragma unroll
        for (int j = 0; j < 8; ++j) {
            float a = acc[j];
#pragma unroll
            for (int o = 16; o; o >>= 1) a += __shfl_xor_sync(0xffffffffu, a, o);
            if (lane == 0) g_kq[(8 * bg + j) * HH + r] = a;
        }
    } else {
        zsum_block(zin, 256 + (blk - 128), t);
    }
}

// ---------------------------------------------------------------------------
// k3: raw masked logit. 2048 blocks x 512 threads, warp per row.
// ---------------------------------------------------------------------------
__global__ void __launch_bounds__(512) k3_logits(
    const float* __restrict__ enc, const int* __restrict__ mask)
{
    const int warp = threadIdx.x >> 5, lane = threadIdx.x & 31;
    const int row = blockIdx.x * 16 + warp;
    const int b = row >> 11;
    const float4* e4 = (const float4*)(enc + (size_t)row * HH);
    const float4* kq4 = (const float4*)(g_kq + b * HH);
    float acc = 0.f;
#pragma unroll
    for (int c = lane; c < HH / 4; c += 32) {
        float4 ev = __ldcs(&e4[c]);
        float4 kv = __ldg(&kq4[c]);
        acc += ev.x * kv.x + ev.y * kv.y + ev.z * kv.z + ev.w * kv.w;
    }
#pragma unroll
    for (int o = 16; o; o >>= 1) acc += __shfl_xor_sync(0xffffffffu, acc, o);
    if (lane == 0) {
        float val = acc * 0.03125f;
        if (mask[row] == 0) val = -1e9f;
        g_w[row] = val;
    }
}

// ---------------------------------------------------------------------------
// L4: blocks [0,16)  -> k4: normalize g_w in place (softmax over L).
//     blocks [16,32) -> kF: S[b,:] = (sum of 32 partials) @ Wv
// 512 threads.
// ---------------------------------------------------------------------------
__global__ void __launch_bounds__(512) k4_norm_f(const float* __restrict__ Wv)
{
    __shared__ float red[16];
    __shared__ float sh[ZZ];
    __shared__ float s_max, s_inv;
    const int blk = blockIdx.x;
    const int t = threadIdx.x;

    if (blk < 16) {
        const int b = blk;
        const int warp = t >> 5, lane = t & 31;
        float lg[4];
#pragma unroll
        for (int k = 0; k < 4; ++k) lg[k] = g_w[b * LL + k * 512 + t];

        float m = fmaxf(fmaxf(lg[0], lg[1]), fmaxf(lg[2], lg[3]));
#pragma unroll
        for (int o = 16; o; o >>= 1) m = fmaxf(m, __shfl_xor_sync(0xffffffffu, m, o));
        if (lane == 0) red[warp] = m;
        __syncthreads();
        if (warp == 0 && lane < 16) {
            float v = red[lane];
#pragma unroll
            for (int o = 8; o; o >>= 1) v = fmaxf(v, __shfl_xor_sync(0xffffu, v, o));
            if (lane == 0) s_max = v;
        }
        __syncthreads();
        const float M = s_max;

        float e[4];
        float s = 0.f;
#pragma unroll
        for (int k = 0; k < 4; ++k) { e[k] = __expf(lg[k] - M); s += e[k]; }
#pragma unroll
        for (int o = 16; o; o >>= 1) s += __shfl_xor_sync(0xffffffffu, s, o);
        __syncthreads();
        if (lane == 0) red[warp] = s;
        __syncthreads();
        if (warp == 0 && lane < 16) {
            float v = red[lane];
#pragma unroll
            for (int o = 8; o; o >>= 1) v += __shfl_xor_sync(0xffffu, v, o);
            if (lane == 0) s_inv = 1.f / v;
        }
        __syncthreads();
        const float inv = s_inv;
#pragma unroll
        for (int k = 0; k < 4; ++k) g_w[b * LL + k * 512 + t] = e[k] * inv;
    } else {
        const int b = blk - 16;
        float acc = 0.f;
#pragma unroll
        for (int c = 0; c < 32; ++c) acc += g_part[(c * BB + b) * ZZ + t];
        sh[t] = acc;
        __syncthreads();
        float s = 0.f;
#pragma unroll 8
        for (int c = 0; c < ZZ; ++c) s += sh[c] * Wv[(size_t)c * ZZ + t];
        g_S[b * ZZ + t] = s;
    }
}

// ---------------------------------------------------------------------------
// k5: pure streaming writer. 5120 blocks x 256 threads, 16 float4/thread.
// ---------------------------------------------------------------------------
__global__ void __launch_bounds__(256) k5_write(float* __restrict__ out)
{
    const int blk = blockIdx.x;
    const int t = threadIdx.x;

    if (blk < 4096) {
        const int b = blk >> 8;
        const long long base = (long long)b * (LL * LL / 4)
                             + (long long)(blk & 255) * 4096;
        const int rowbase = (int)(base >> 9);
        float4* attn4 = (float4*)(out + (size_t)BB * LL * ZZ);
        float w8[8];
#pragma unroll
        for (int j = 0; j < 8; ++j) w8[j] = __ldg(&g_w[rowbase + j]);
#pragma unroll
        for (int k = 0; k < 16; ++k) {
            const float wv = w8[k >> 1];
            __stcs(attn4 + base + k * 256 + t, make_float4(wv, wv, wv, wv));
        }
    } else {
        const int e = blk - 4096;
        const int b = e >> 6;
        const long long base = (long long)b * (LL * ZZ / 4)
                             + (long long)(e & 63) * 4096;
        const int rowbase = (int)(base >> 7);
        const int rsub = t >> 7;
        const float4 sv = __ldg((const float4*)g_S + b * (ZZ / 4) + (t & 127));
#pragma unroll
        for (int k = 0; k < 16; ++k) {
            const float wv = __ldg(&g_w[rowbase + 2 * k + rsub]);
            __stcs((float4*)out + base + k * 256 + t,
                   make_float4(wv * sv.x, wv * sv.y, wv * sv.z, wv * sv.w));
        }
    }
}

// ---------------------------------------------------------------------------
extern "C" void kernel_launch(void* const* d_in, const int* in_sizes, int n_in,
                              void* d_out, int out_size)
{
    const float* enc  = (const float*)d_in[0];
    const float* fin  = (const float*)d_in[1];
    const float* zseq = (const float*)d_in[2];
    const int*   mask = (const int*)  d_in[3];
    const float* Wq   = (const float*)d_in[4];
    const float* Wk   = (const float*)d_in[5];
    const float* Wv   = (const float*)d_in[6];
    float* out = (float*)d_out;

    k1_a_e<<<384, 512>>>(fin, Wk, zseq);   // kA + first half of z-sum
    k2_b_e<<<384, 512>>>(Wq, zseq);        // kB (batch-shared) + second half
    k3_logits<<<2048, 512>>>(enc, mask);
    k4_norm_f<<<32, 512>>>(Wv);            // softmax normalize + S projection
    k5_write<<<5120, 256>>>(out);
}

// round 7
// speedup vs baseline: 1.1224x; 1.1114x over previous
#include <cuda_runtime.h>

#define BB 16
#define LL 2048
#define HH 1024
#define ZZ 512

// Scratch (device globals; no allocation allowed)
__device__ float g_k[BB * HH];          // final @ Wk
__device__ float g_kq[BB * HH];         // Wq @ k
__device__ float g_w[BB * LL];          // logits, then NORMALIZED softmax weights
__device__ float g_part[32 * BB * ZZ];  // partial column sums of latent z
__device__ float g_S2[8 * BB * ZZ];     // split-K partials of S
__device__ float g_S[BB * ZZ];          // (sum_i z[b,i]) @ Wv

// ---------------------------------------------------------------------------
// kE helper: one block = one (batch, 64-row chunk) partial column sum of z.
// ---------------------------------------------------------------------------
__device__ __forceinline__ void zsum_block(const float* __restrict__ zin, int e, int t)
{
    const int b = e >> 5;
    const int chunk = e & 31;
    const float* base = zin + ((size_t)b * LL + (size_t)chunk * 64) * ZZ + t;
    float acc = 0.f;
#pragma unroll 16
    for (int i = 0; i < 64; ++i) acc += __ldcs(base + (size_t)i * ZZ);
    g_part[(chunk * BB + b) * ZZ + t] = acc;
}

// ---------------------------------------------------------------------------
// L1: blocks [0,128)   -> kA: k[b,h] = fin[b,:] . Wk[:,h]
//     blocks [128,384) -> kE chunks [0,256)
// ---------------------------------------------------------------------------
__global__ void __launch_bounds__(512) k1_a_e(
    const float* __restrict__ fin, const float* __restrict__ Wk,
    const float* __restrict__ zin)
{
    __shared__ float sh[HH];
    __shared__ float red[512];
    const int blk = blockIdx.x;
    const int t = threadIdx.x;

    if (blk < 128) {
        const int b = blk >> 3;
        const int hof = t & 127;
        const int h = ((blk & 7) << 7) + hof;
        const int cs = t >> 7;
        for (int j = t; j < HH; j += 512) sh[j] = fin[b * HH + j];
        __syncthreads();
        float acc = 0.f;
        const float* wcol = Wk + h;
#pragma unroll 8
        for (int c = cs * 256; c < (cs + 1) * 256; ++c)
            acc += sh[c] * wcol[(size_t)c * HH];
        red[t] = acc;
        __syncthreads();
        if (cs == 0)
            g_k[b * HH + h] = red[hof] + red[128 + hof] + red[256 + hof] + red[384 + hof];
    } else {
        zsum_block(zin, blk - 128, t);
    }
}

// ---------------------------------------------------------------------------
// L2: blocks [0,128)   -> kB batch-shared (8 k-vectors in smem per block)
//     blocks [128,384) -> kE chunks [256,512)
// ---------------------------------------------------------------------------
__global__ void __launch_bounds__(512) k2_b_e(
    const float* __restrict__ Wq, const float* __restrict__ zin)
{
    __shared__ __align__(16) float sk[8 * HH];      // 32 KB
    const int blk = blockIdx.x;
    const int t = threadIdx.x;

    if (blk < 128) {
        const int rb = blk >> 1;
        const int bg = blk & 1;
        for (int j = t; j < 8 * HH; j += 512)
            sk[j] = g_k[(8 * bg + (j >> 10)) * HH + (j & 1023)];
        __syncthreads();

        const int warp = t >> 5, lane = t & 31;
        const int r = rb * 16 + warp;
        const float4* wrow = (const float4*)(Wq + (size_t)r * HH);
        float acc[8] = {0.f, 0.f, 0.f, 0.f, 0.f, 0.f, 0.f, 0.f};
#pragma unroll 2
        for (int c = lane; c < HH / 4; c += 32) {
            const float4 wv = wrow[c];
#pragma unroll
            for (int j = 0; j < 8; ++j) {
                const float4 kv = ((const float4*)(sk + j * HH))[c];
                acc[j] += wv.x * kv.x + wv.y * kv.y + wv.z * kv.z + wv.w * kv.w;
            }
        }
#pragma unroll
        for (int j = 0; j < 8; ++j) {
            float a = acc[j];
#pragma unroll
            for (int o = 16; o; o >>= 1) a += __shfl_xor_sync(0xffffffffu, a, o);
            if (lane == 0) g_kq[(8 * bg + j) * HH + r] = a;
        }
    } else {
        zsum_block(zin, 256 + (blk - 128), t);
    }
}

// ---------------------------------------------------------------------------
// L3: blocks [0,2048)     -> logits (warp per row, BW-bound, 134 MB)
//     blocks [2048,2176)  -> kF split-K partials: block (b, slice) computes
//                            S2[slice,b,t] = sum_{c in 64-slice} zsum[b,c]*Wv[c,t]
// ---------------------------------------------------------------------------
__global__ void __launch_bounds__(512) k3_logits_f(
    const float* __restrict__ enc, const int* __restrict__ mask,
    const float* __restrict__ Wv)
{
    __shared__ float zs[64];
    const int blk = blockIdx.x;
    const int t = threadIdx.x;

    if (blk < 2048) {
        const int warp = t >> 5, lane = t & 31;
        const int row = blk * 16 + warp;
        const int b = row >> 11;
        const float4* e4 = (const float4*)(enc + (size_t)row * HH);
        const float4* kq4 = (const float4*)(g_kq + b * HH);
        float acc = 0.f;
#pragma unroll
        for (int c = lane; c < HH / 4; c += 32) {
            float4 ev = __ldcs(&e4[c]);
            float4 kv = __ldg(&kq4[c]);
            acc += ev.x * kv.x + ev.y * kv.y + ev.z * kv.z + ev.w * kv.w;
        }
#pragma unroll
        for (int o = 16; o; o >>= 1) acc += __shfl_xor_sync(0xffffffffu, acc, o);
        if (lane == 0) {
            float val = acc * 0.03125f;
            if (mask[row] == 0) val = -1e9f;
            g_w[row] = val;
        }
    } else {
        const int e = blk - 2048;        // 0..127
        const int b = e >> 3;            // batch
        const int slice = e & 7;         // 64-c slice

        // zs[c_local] = zsum[b][64*slice + c_local]: 8 threads per c, 4 chunks each
        const int cl = t >> 3;           // 0..63
        const int sub = t & 7;           // 0..7
        const int c = 64 * slice + cl;
        float a = 0.f;
#pragma unroll
        for (int j = 0; j < 4; ++j)
            a += g_part[((sub + 8 * j) * BB + b) * ZZ + c];
#pragma unroll
        for (int o = 4; o; o >>= 1) a += __shfl_xor_sync(0xffffffffu, a, o);
        if (sub == 0) zs[cl] = a;
        __syncthreads();

        // partial S: 64 FMA-loads from Wv (L2-resident)
        float s = 0.f;
        const float* wbase = Wv + (size_t)(64 * slice) * ZZ + t;
#pragma unroll 8
        for (int c2 = 0; c2 < 64; ++c2)
            s += zs[c2] * wbase[(size_t)c2 * ZZ];
        g_S2[(slice * BB + b) * ZZ + t] = s;
    }
}

// ---------------------------------------------------------------------------
// L4: blocks [0,16)  -> softmax normalize g_w in place
//     blocks [16,32) -> final S reduce over 8 split-K partials
// ---------------------------------------------------------------------------
__global__ void __launch_bounds__(512) k4_norm_red()
{
    __shared__ float red[16];
    __shared__ float s_max, s_inv;
    const int blk = blockIdx.x;
    const int t = threadIdx.x;

    if (blk < 16) {
        const int b = blk;
        const int warp = t >> 5, lane = t & 31;
        float lg[4];
#pragma unroll
        for (int k = 0; k < 4; ++k) lg[k] = g_w[b * LL + k * 512 + t];

        float m = fmaxf(fmaxf(lg[0], lg[1]), fmaxf(lg[2], lg[3]));
#pragma unroll
        for (int o = 16; o; o >>= 1) m = fmaxf(m, __shfl_xor_sync(0xffffffffu, m, o));
        if (lane == 0) red[warp] = m;
        __syncthreads();
        if (warp == 0 && lane < 16) {
            float v = red[lane];
#pragma unroll
            for (int o = 8; o; o >>= 1) v = fmaxf(v, __shfl_xor_sync(0xffffu, v, o));
            if (lane == 0) s_max = v;
        }
        __syncthreads();
        const float M = s_max;

        float e[4];
        float s = 0.f;
#pragma unroll
        for (int k = 0; k < 4; ++k) { e[k] = __expf(lg[k] - M); s += e[k]; }
#pragma unroll
        for (int o = 16; o; o >>= 1) s += __shfl_xor_sync(0xffffffffu, s, o);
        __syncthreads();
        if (lane == 0) red[warp] = s;
        __syncthreads();
        if (warp == 0 && lane < 16) {
            float v = red[lane];
#pragma unroll
            for (int o = 8; o; o >>= 1) v += __shfl_xor_sync(0xffffu, v, o);
            if (lane == 0) s_inv = 1.f / v;
        }
        __syncthreads();
        const float inv = s_inv;
#pragma unroll
        for (int k = 0; k < 4; ++k) g_w[b * LL + k * 512 + t] = e[k] * inv;
    } else {
        const int b = blk - 16;
        float s = 0.f;
#pragma unroll
        for (int k = 0; k < 8; ++k) s += g_S2[(k * BB + b) * ZZ + t];
        g_S[b * ZZ + t] = s;
    }
}

// ---------------------------------------------------------------------------
// k5: pure streaming writer. 5120 blocks x 256 threads, 16 float4/thread.
// ---------------------------------------------------------------------------
__global__ void __launch_bounds__(256) k5_write(float* __restrict__ out)
{
    const int blk = blockIdx.x;
    const int t = threadIdx.x;

    if (blk < 4096) {
        const int b = blk >> 8;
        const long long base = (long long)b * (LL * LL / 4)
                             + (long long)(blk & 255) * 4096;
        const int rowbase = (int)(base >> 9);
        float4* attn4 = (float4*)(out + (size_t)BB * LL * ZZ);
        float w8[8];
#pragma unroll
        for (int j = 0; j < 8; ++j) w8[j] = __ldg(&g_w[rowbase + j]);
#pragma unroll
        for (int k = 0; k < 16; ++k) {
            const float wv = w8[k >> 1];
            __stcs(attn4 + base + k * 256 + t, make_float4(wv, wv, wv, wv));
        }
    } else {
        const int e = blk - 4096;
        const int b = e >> 6;
        const long long base = (long long)b * (LL * ZZ / 4)
                             + (long long)(e & 63) * 4096;
        const int rowbase = (int)(base >> 7);
        const int rsub = t >> 7;
        const float4 sv = __ldg((const float4*)g_S + b * (ZZ / 4) + (t & 127));
#pragma unroll
        for (int k = 0; k < 16; ++k) {
            const float wv = __ldg(&g_w[rowbase + 2 * k + rsub]);
            __stcs((float4*)out + base + k * 256 + t,
                   make_float4(wv * sv.x, wv * sv.y, wv * sv.z, wv * sv.w));
        }
    }
}

// ---------------------------------------------------------------------------
extern "C" void kernel_launch(void* const* d_in, const int* in_sizes, int n_in,
                              void* d_out, int out_size)
{
    const float* enc  = (const float*)d_in[0];
    const float* fin  = (const float*)d_in[1];
    const float* zseq = (const float*)d_in[2];
    const int*   mask = (const int*)  d_in[3];
    const float* Wq   = (const float*)d_in[4];
    const float* Wk   = (const float*)d_in[5];
    const float* Wv   = (const float*)d_in[6];
    float* out = (float*)d_out;

    k1_a_e<<<384, 512>>>(fin, Wk, zseq);       // kA + z-sum half 1
    k2_b_e<<<384, 512>>>(Wq, zseq);            // kB + z-sum half 2
    k3_logits_f<<<2176, 512>>>(enc, mask, Wv); // logits + hidden kF split-K
    k4_norm_red<<<32, 512>>>();                // softmax norm + S reduce
    k5_write<<<5120, 256>>>(out);
}

// round 8
// speedup vs baseline: 1.1293x; 1.0061x over previous
#include <cuda_runtime.h>

#define BB 16
#define LL 2048
#define HH 1024
#define ZZ 512

// Scratch (device globals; no allocation allowed)
__device__ float g_k[BB * HH];          // final @ Wk
__device__ float g_kq[BB * HH];         // Wq @ k
__device__ float g_w[BB * LL];          // RAW masked logits (softmax done in k5)
__device__ float g_part[32 * BB * ZZ];  // partial column sums of latent z
__device__ float g_S2[8 * BB * ZZ];     // split-K partials of S (reduced in k5)

// ---------------------------------------------------------------------------
// kE helper: one block = one (batch, 64-row chunk) partial column sum of z.
// ---------------------------------------------------------------------------
__device__ __forceinline__ void zsum_block(const float* __restrict__ zin, int e, int t)
{
    const int b = e >> 5;
    const int chunk = e & 31;
    const float* base = zin + ((size_t)b * LL + (size_t)chunk * 64) * ZZ + t;
    float acc = 0.f;
#pragma unroll 16
    for (int i = 0; i < 64; ++i) acc += __ldcs(base + (size_t)i * ZZ);
    g_part[(chunk * BB + b) * ZZ + t] = acc;
}

// ---------------------------------------------------------------------------
// L1: blocks [0,128)   -> kA: k[b,h] = fin[b,:] . Wk[:,h]
//     blocks [128,384) -> kE chunks [0,256)
// ---------------------------------------------------------------------------
__global__ void __launch_bounds__(512) k1_a_e(
    const float* __restrict__ fin, const float* __restrict__ Wk,
    const float* __restrict__ zin)
{
    __shared__ float sh[HH];
    __shared__ float red[512];
    const int blk = blockIdx.x;
    const int t = threadIdx.x;

    if (blk < 128) {
        const int b = blk >> 3;
        const int hof = t & 127;
        const int h = ((blk & 7) << 7) + hof;
        const int cs = t >> 7;
        for (int j = t; j < HH; j += 512) sh[j] = fin[b * HH + j];
        __syncthreads();
        float acc = 0.f;
        const float* wcol = Wk + h;
#pragma unroll 8
        for (int c = cs * 256; c < (cs + 1) * 256; ++c)
            acc += sh[c] * wcol[(size_t)c * HH];
        red[t] = acc;
        __syncthreads();
        if (cs == 0)
            g_k[b * HH + h] = red[hof] + red[128 + hof] + red[256 + hof] + red[384 + hof];
    } else {
        zsum_block(zin, blk - 128, t);
    }
}

// ---------------------------------------------------------------------------
// L2: blocks [0,128)   -> kB batch-shared (8 k-vectors in smem per block)
//     blocks [128,384) -> kE chunks [256,512)
// ---------------------------------------------------------------------------
__global__ void __launch_bounds__(512) k2_b_e(
    const float* __restrict__ Wq, const float* __restrict__ zin)
{
    __shared__ __align__(16) float sk[8 * HH];      // 32 KB
    const int blk = blockIdx.x;
    const int t = threadIdx.x;

    if (blk < 128) {
        const int rb = blk >> 1;
        const int bg = blk & 1;
        for (int j = t; j < 8 * HH; j += 512)
            sk[j] = g_k[(8 * bg + (j >> 10)) * HH + (j & 1023)];
        __syncthreads();

        const int warp = t >> 5, lane = t & 31;
        const int r = rb * 16 + warp;
        const float4* wrow = (const float4*)(Wq + (size_t)r * HH);
        float acc[8] = {0.f, 0.f, 0.f, 0.f, 0.f, 0.f, 0.f, 0.f};
#pragma unroll 2
        for (int c = lane; c < HH / 4; c += 32) {
            const float4 wv = wrow[c];
#pragma unroll
            for (int j = 0; j < 8; ++j) {
                const float4 kv = ((const float4*)(sk + j * HH))[c];
                acc[j] += wv.x * kv.x + wv.y * kv.y + wv.z * kv.z + wv.w * kv.w;
            }
        }
#pragma unroll
        for (int j = 0; j < 8; ++j) {
            float a = acc[j];
#pragma unroll
            for (int o = 16; o; o >>= 1) a += __shfl_xor_sync(0xffffffffu, a, o);
            if (lane == 0) g_kq[(8 * bg + j) * HH + r] = a;
        }
    } else {
        zsum_block(zin, 256 + (blk - 128), t);
    }
}

// ---------------------------------------------------------------------------
// L3: blocks [0,2048)     -> raw masked logits (warp per row, BW-bound)
//     blocks [2048,2176)  -> kF split-K: S2[slice,b,t] over 64-c slices
// ---------------------------------------------------------------------------
__global__ void __launch_bounds__(512) k3_logits_f(
    const float* __restrict__ enc, const int* __restrict__ mask,
    const float* __restrict__ Wv)
{
    __shared__ float zs[64];
    const int blk = blockIdx.x;
    const int t = threadIdx.x;

    if (blk < 2048) {
        const int warp = t >> 5, lane = t & 31;
        const int row = blk * 16 + warp;
        const int b = row >> 11;
        const float4* e4 = (const float4*)(enc + (size_t)row * HH);
        const float4* kq4 = (const float4*)(g_kq + b * HH);
        float acc = 0.f;
#pragma unroll
        for (int c = lane; c < HH / 4; c += 32) {
            float4 ev = __ldcs(&e4[c]);
            float4 kv = __ldg(&kq4[c]);
            acc += ev.x * kv.x + ev.y * kv.y + ev.z * kv.z + ev.w * kv.w;
        }
#pragma unroll
        for (int o = 16; o; o >>= 1) acc += __shfl_xor_sync(0xffffffffu, acc, o);
        if (lane == 0) {
            float val = acc * 0.03125f;
            if (mask[row] == 0) val = -1e9f;
            g_w[row] = val;
        }
    } else {
        const int e = blk - 2048;        // 0..127
        const int b = e >> 3;
        const int slice = e & 7;

        const int cl = t >> 3;           // 0..63
        const int sub = t & 7;           // 0..7
        const int c = 64 * slice + cl;
        float a = 0.f;
#pragma unroll
        for (int j = 0; j < 4; ++j)
            a += g_part[((sub + 8 * j) * BB + b) * ZZ + c];
#pragma unroll
        for (int o = 4; o; o >>= 1) a += __shfl_xor_sync(0xffffffffu, a, o);
        if (sub == 0) zs[cl] = a;
        __syncthreads();

        float s = 0.f;
        const float* wbase = Wv + (size_t)(64 * slice) * ZZ + t;
#pragma unroll 8
        for (int c2 = 0; c2 < 64; ++c2)
            s += zs[c2] * wbase[(size_t)c2 * ZZ];
        g_S2[(slice * BB + b) * ZZ + t] = s;
    }
}

// ---------------------------------------------------------------------------
// k5: fused softmax + S-reduce + streaming writer. 5120 blocks x 256 threads.
// Per-block preamble: softmax stats (M, inv) of this block's batch from L2
// (proven free under the store stream in R3). Out-blocks additionally reduce
// the 8 split-K S2 partials for their column. 16 float4 stores per thread.
//   blocks [0,4096)    : attn (8 rows/block, normalized weights hoisted)
//   blocks [4096,5120) : out (32 rows/block, reduced S float4 hoisted)
// ---------------------------------------------------------------------------
__global__ void __launch_bounds__(256) k5_write(float* __restrict__ out)
{
    __shared__ float red[8];
    __shared__ float s_max, s_inv;
    const int blk = blockIdx.x;
    const int t = threadIdx.x;
    const int warp = t >> 5, lane = t & 31;

    const bool is_attn = (blk < 4096);
    const int b = is_attn ? (blk >> 8) : ((blk - 4096) >> 6);

    // ---- softmax stats over this batch's 2048 raw logits ----
    float lg[8];
#pragma unroll
    for (int k = 0; k < 8; ++k) lg[k] = __ldg(&g_w[b * LL + k * 256 + t]);

    float m = lg[0];
#pragma unroll
    for (int k = 1; k < 8; ++k) m = fmaxf(m, lg[k]);
#pragma unroll
    for (int o = 16; o; o >>= 1) m = fmaxf(m, __shfl_xor_sync(0xffffffffu, m, o));
    if (lane == 0) red[warp] = m;
    __syncthreads();
    if (warp == 0 && lane < 8) {
        float v = red[lane];
#pragma unroll
        for (int o = 4; o; o >>= 1) v = fmaxf(v, __shfl_xor_sync(0xffu, v, o));
        if (lane == 0) s_max = v;
    }
    __syncthreads();
    const float M = s_max;

    float s = 0.f;
#pragma unroll
    for (int k = 0; k < 8; ++k) s += __expf(lg[k] - M);   // masked rows -> 0
#pragma unroll
    for (int o = 16; o; o >>= 1) s += __shfl_xor_sync(0xffffffffu, s, o);
    __syncthreads();
    if (lane == 0) red[warp] = s;
    __syncthreads();
    if (warp == 0 && lane < 8) {
        float v = red[lane];
#pragma unroll
        for (int o = 4; o; o >>= 1) v += __shfl_xor_sync(0xffu, v, o);
        if (lane == 0) s_inv = 1.f / v;
    }
    __syncthreads();
    const float inv = s_inv;

    // ---- 16 streaming float4 stores per thread ----
    if (is_attn) {
        const long long base = (long long)b * (LL * LL / 4)
                             + (long long)(blk & 255) * 4096;
        const int rowbase = (int)(base >> 9);
        float4* attn4 = (float4*)(out + (size_t)BB * LL * ZZ);
        float w8[8];
#pragma unroll
        for (int j = 0; j < 8; ++j)
            w8[j] = __expf(__ldg(&g_w[rowbase + j]) - M) * inv;
#pragma unroll
        for (int k = 0; k < 16; ++k) {
            const float wv = w8[k >> 1];
            __stcs(attn4 + base + k * 256 + t, make_float4(wv, wv, wv, wv));
        }
    } else {
        const int e = blk - 4096;
        const long long base = (long long)b * (LL * ZZ / 4)
                             + (long long)(e & 63) * 4096;
        const int rowbase = (int)(base >> 7);
        const int rsub = t >> 7;
        const int col = t & 127;
        // reduce 8 split-K partials of S for this column (g_S2 is L2-resident)
        const float4* S24 = (const float4*)g_S2;
        float4 sv = make_float4(0.f, 0.f, 0.f, 0.f);
#pragma unroll
        for (int k = 0; k < 8; ++k) {
            const float4 p = __ldg(&S24[(k * BB + b) * (ZZ / 4) + col]);
            sv.x += p.x; sv.y += p.y; sv.z += p.z; sv.w += p.w;
        }
#pragma unroll
        for (int k = 0; k < 16; ++k) {
            const float wv = __expf(__ldg(&g_w[rowbase + 2 * k + rsub]) - M) * inv;
            __stcs((float4*)out + base + k * 256 + t,
                   make_float4(wv * sv.x, wv * sv.y, wv * sv.z, wv * sv.w));
        }
    }
}

// ---------------------------------------------------------------------------
extern "C" void kernel_launch(void* const* d_in, const int* in_sizes, int n_in,
                              void* d_out, int out_size)
{
    const float* enc  = (const float*)d_in[0];
    const float* fin  = (const float*)d_in[1];
    const float* zseq = (const float*)d_in[2];
    const int*   mask = (const int*)  d_in[3];
    const float* Wq   = (const float*)d_in[4];
    const float* Wk   = (const float*)d_in[5];
    const float* Wv   = (const float*)d_in[6];
    float* out = (float*)d_out;

    k1_a_e<<<384, 512>>>(fin, Wk, zseq);       // kA + z-sum half 1
    k2_b_e<<<384, 512>>>(Wq, zseq);            // kB + z-sum half 2
    k3_logits_f<<<2176, 512>>>(enc, mask, Wv); // logits + hidden kF split-K
    k5_write<<<5120, 256>>>(out);              // softmax + S-reduce + write
}